// round 14
// baseline (speedup 1.0000x reference)
#include <cuda_runtime.h>
#include <math.h>

#define NBATCH 4
#define NATOM  512
#define NSYM   4
#define NLAB   16
#define C1     32
#define C2     64
#define NTHR   128
#define GA     2          // atoms per CTA
#define MAXNB  96
#define C0P    36         // padded centres0 row (floats); 144B rows, 16B-aligned
#define C1P    68         // padded centres1 row (floats); 272B rows, 16B-aligned
#define SQK    1.2011224087864498f   // sqrt(log2(e))

typedef unsigned long long u64;

__device__ __forceinline__ float ex2(float x) {
    float r; asm("ex2.approx.ftz.f32 %0, %1;" : "=f"(r) : "f"(x)); return r;
}
__device__ __forceinline__ u64 pk2(float lo, float hi) {
    u64 r; asm("mov.b64 %0, {%1, %2};" : "=l"(r) : "f"(lo), "f"(hi)); return r;
}
__device__ __forceinline__ u64 fma2(u64 a, u64 b, u64 c) {
    u64 r; asm("fma.rn.f32x2 %0, %1, %2, %3;" : "=l"(r) : "l"(a), "l"(b), "l"(c)); return r;
}
__device__ __forceinline__ u64 mul2(u64 a, u64 b) {
    u64 r; asm("mul.rn.f32x2 %0, %1, %2;" : "=l"(r) : "l"(a), "l"(b)); return r;
}

__global__ __launch_bounds__(NTHR)
void descriptor_kernel(const int*   __restrict__ numbers,
                       const float* __restrict__ coords,
                       const float* __restrict__ nuww0,
                       const float* __restrict__ sigmas0,
                       const float* __restrict__ centres0,
                       const float* __restrict__ nuww1,
                       const float* __restrict__ sigmas1,
                       const float* __restrict__ centres1,
                       float*       __restrict__ out)
{
    __shared__ float4 s_pos[NATOM];                  // 8 KB
    __shared__ float  s_c0s[NLAB * C0P];             // 2.25 KB (c0*s0*SQK, padded)
    __shared__ float  s_sc1[NLAB * C1P];             // 4.25 KB (c1*s1*SQK, padded)
    __shared__ float  s_w0[NLAB], s_s0f[NLAB], s_w1[NLAB], s_s1f[NLAB];
    __shared__ float4 nb_f4[GA][MAXNB];              // 3 KB  (w1*fc, w1*gx, w1*gy, w1*gz)
    __shared__ float2 nb_meta[GA][MAXNB];            // 1.5 KB (rs*s1*SQK, row offset)
    __shared__ int    nb_j[GA][MAXNB];               // 0.75 KB (neighbor index only)
    __shared__ float4 LmTf [GA][C2];                 // 2 KB  f-minor: [c2] -> (f0..f3)
    __shared__ float4 LmTsf[GA][C2];                 // 2 KB  rf-scaled copy, same layout
    __shared__ int    s_wcnt[GA][4];

    const int tid  = threadIdx.x;
    const int bidx = blockIdx.x;
    const int b    = bidx >> 8;                      // 256 CTAs per batch
    const int li0  = (bidx & 255) * GA;
    const int lane = tid & 31;
    const int warp = tid >> 5;
    const int g    = tid >> 6;                       // atom served (0/1) in later phases
    const int t64  = tid & 63;

    // ---- cooperative loads + folded table pre-scaling (float4 paths) ----
    {
        const float* cb  = coords  + (size_t)b * NATOM * 3;
        const int*   nbp = numbers + (size_t)b * NATOM;
        for (int t = tid; t < NATOM; t += NTHR)
            s_pos[t] = make_float4(cb[t * 3 + 0], cb[t * 3 + 1], cb[t * 3 + 2],
                                   __int_as_float(nbp[t]));
        // centres0: 512 floats = 128 float4, one sweep
        {
            const float4 v = reinterpret_cast<const float4*>(centres0)[tid];
            const int lab = tid >> 3;                // 8 float4 per row
            const float s = sigmas0[lab] * SQK;
            *reinterpret_cast<float4*>(&s_c0s[lab * C0P + (tid & 7) * 4]) =
                make_float4(v.x * s, v.y * s, v.z * s, v.w * s);
        }
        // centres1: 1024 floats = 256 float4, two sweeps
        #pragma unroll
        for (int r = 0; r < 2; r++) {
            const int idx = tid + r * NTHR;
            const float4 v = reinterpret_cast<const float4*>(centres1)[idx];
            const int lab = idx >> 4;                // 16 float4 per row
            const float s = sigmas1[lab] * SQK;
            *reinterpret_cast<float4*>(&s_sc1[lab * C1P + (idx & 15) * 4]) =
                make_float4(v.x * s, v.y * s, v.z * s, v.w * s);
        }
        if (tid < NLAB) {
            s_w0[tid]  = nuww0[tid];  s_s0f[tid] = sigmas0[tid] * SQK;
            s_w1[tid]  = nuww1[tid];  s_s1f[tid] = sigmas1[tid] * SQK;
        }
    }
    __syncthreads();

    // ---- Phase 1a: shared-j test + index-only compaction ----
    {
        const float4 ci0 = s_pos[li0];
        const float4 ci1 = s_pos[li0 + 1];

        unsigned mk0[4], mk1[4];
        int cnt0 = 0, cnt1 = 0;
        #pragma unroll
        for (int c = 0; c < 4; c++) {
            const int j = warp * 128 + c * 32 + lane;
            const float4 p = s_pos[j];
            const float dx0 = p.x - ci0.x, dy0 = p.y - ci0.y, dz0 = p.z - ci0.z;
            const float dx1 = p.x - ci1.x, dy1 = p.y - ci1.y, dz1 = p.z - ci1.z;
            const float d20 = dx0 * dx0 + dy0 * dy0 + dz0 * dz0;
            const float d21 = dx1 * dx1 + dy1 * dy1 + dz1 * dz1;
            const bool f0 = (j != li0)     && (d20 <= 36.0f);
            const bool f1 = (j != li0 + 1) && (d21 <= 36.0f);
            mk0[c] = __ballot_sync(0xffffffffu, f0);
            mk1[c] = __ballot_sync(0xffffffffu, f1);
            cnt0 += __popc(mk0[c]);
            cnt1 += __popc(mk1[c]);
        }
        if (lane == 0) { s_wcnt[0][warp] = cnt0; s_wcnt[1][warp] = cnt1; }
        __syncthreads();

        int base0 = 0, base1 = 0;
        #pragma unroll
        for (int w = 0; w < 4; w++) {
            if (w < warp) { base0 += s_wcnt[0][w]; base1 += s_wcnt[1][w]; }
        }
        const unsigned ltmask = (1u << lane) - 1u;
        #pragma unroll
        for (int c = 0; c < 4; c++) {
            const int j = warp * 128 + c * 32 + lane;
            if ((mk0[c] >> lane) & 1u) {
                const int pos = base0 + __popc(mk0[c] & ltmask);
                if (pos < MAXNB) nb_j[0][pos] = j;
            }
            base0 += __popc(mk0[c]);
            if ((mk1[c] >> lane) & 1u) {
                const int pos = base1 + __popc(mk1[c] & ltmask);
                if (pos < MAXNB) nb_j[1][pos] = j;
            }
            base1 += __popc(mk1[c]);
        }
    }
    __syncthreads();

    const int nnb = min(s_wcnt[g][0] + s_wcnt[g][1] +
                        s_wcnt[g][2] + s_wcnt[g][3], MAXNB);

    // ---- Phase 1b: geometry + first RConv (4 thr/pair, 16 pairs/sweep) ----
    {
        const float4 ci = s_pos[li0 + g];
        const int zbase = __float_as_int(ci.w) * NSYM;
        const int sub  = t64 & 3;                    // channel group of 8
        const int slot = t64 >> 2;                   // 0..15
        const int nIter = (nnb + 15) >> 4;           // warp-uniform (same g per warp)
        for (int it = 0; it < nIter; it++) {
            const int p  = slot + (it << 4);
            const int pc = (p < nnb) ? p : (nnb - 1);
            const int j  = nb_j[g][pc];
            const float4 pj = s_pos[j];
            const float dx = pj.x - ci.x, dy = pj.y - ci.y, dz = pj.z - ci.z;
            const float d2 = dx * dx + dy * dy + dz * dz;
            const float rinv = (d2 > 0.0f) ? rsqrtf(d2) : 0.0f;
            const float d    = d2 * rinv;
            const float fc   = 0.5f * __cosf(d * 0.52359877559829887f) + 0.5f;
            const int   lab  = zbase + __float_as_int(pj.w);
            const float fcs  = fc * s_s0f[lab];
            const float4 cA = *reinterpret_cast<const float4*>(&s_c0s[lab * C0P + sub * 8]);
            const float4 cB = *reinterpret_cast<const float4*>(&s_c0s[lab * C0P + sub * 8 + 4]);
            const float a0 = fcs - cA.x, a1 = fcs - cA.y, a2 = fcs - cA.z, a3 = fcs - cA.w;
            const float a4 = fcs - cB.x, a5 = fcs - cB.y, a6 = fcs - cB.z, a7 = fcs - cB.w;
            float sum = ex2(-a0 * a0) + ex2(-a1 * a1) + ex2(-a2 * a2) + ex2(-a3 * a3)
                      + ex2(-a4 * a4) + ex2(-a5 * a5) + ex2(-a6 * a6) + ex2(-a7 * a7);
            sum += __shfl_xor_sync(0xffffffffu, sum, 1);
            sum += __shfl_xor_sync(0xffffffffu, sum, 2);
            if (sub == 0 && p < nnb) {
                const float w1 = s_w1[lab];
                const float rs = s_w0[lab] * sum;
                nb_meta[g][p] = make_float2(rs * s_s1f[lab],
                                            __int_as_float(lab * C1P));
                const float gg = rinv * fc * w1;
                nb_f4[g][p] = make_float4(fc * w1, dx * gg, dy * gg, dz * gg);
            }
        }
    }
    __syncthreads();

    // ---- Phase 2: second RConv + Lm. 4 c2 x 4 neighbor-slices, scalar FMA ----
    {
        const int lw    = t64 >> 5;
        const int l5    = t64 & 31;
        const int grp   = l5 >> 2;
        const int slice = l5 & 3;
        const int c2b   = (lw * 8 + grp) * 4;

        float acc[4][4];                             // [c2i][f]
        #pragma unroll
        for (int a = 0; a < 4; a++)
            #pragma unroll
            for (int f = 0; f < 4; f++) acc[a][f] = 0.0f;

        int k = slice;
        for (; k + 4 < nnb; k += 8) {
            const float2 mA = nb_meta[g][k];
            const float2 mB = nb_meta[g][k + 4];
            const float4 ccA = *reinterpret_cast<const float4*>(
                &s_sc1[__float_as_int(mA.y) + c2b]);
            const float4 ccB = *reinterpret_cast<const float4*>(
                &s_sc1[__float_as_int(mB.y) + c2b]);
            const float tA0 = mA.x - ccA.x, tA1 = mA.x - ccA.y;
            const float tA2 = mA.x - ccA.z, tA3 = mA.x - ccA.w;
            const float tB0 = mB.x - ccB.x, tB1 = mB.x - ccB.y;
            const float tB2 = mB.x - ccB.z, tB3 = mB.x - ccB.w;
            const float pA0 = ex2(-tA0 * tA0), pA1 = ex2(-tA1 * tA1);
            const float pA2 = ex2(-tA2 * tA2), pA3 = ex2(-tA3 * tA3);
            const float pB0 = ex2(-tB0 * tB0), pB1 = ex2(-tB1 * tB1);
            const float pB2 = ex2(-tB2 * tB2), pB3 = ex2(-tB3 * tB3);
            const float4 fA = nb_f4[g][k];
            const float4 fB = nb_f4[g][k + 4];
            acc[0][0] = fmaf(pA0, fA.x, acc[0][0]); acc[0][1] = fmaf(pA0, fA.y, acc[0][1]);
            acc[0][2] = fmaf(pA0, fA.z, acc[0][2]); acc[0][3] = fmaf(pA0, fA.w, acc[0][3]);
            acc[1][0] = fmaf(pA1, fA.x, acc[1][0]); acc[1][1] = fmaf(pA1, fA.y, acc[1][1]);
            acc[1][2] = fmaf(pA1, fA.z, acc[1][2]); acc[1][3] = fmaf(pA1, fA.w, acc[1][3]);
            acc[2][0] = fmaf(pA2, fA.x, acc[2][0]); acc[2][1] = fmaf(pA2, fA.y, acc[2][1]);
            acc[2][2] = fmaf(pA2, fA.z, acc[2][2]); acc[2][3] = fmaf(pA2, fA.w, acc[2][3]);
            acc[3][0] = fmaf(pA3, fA.x, acc[3][0]); acc[3][1] = fmaf(pA3, fA.y, acc[3][1]);
            acc[3][2] = fmaf(pA3, fA.z, acc[3][2]); acc[3][3] = fmaf(pA3, fA.w, acc[3][3]);
            acc[0][0] = fmaf(pB0, fB.x, acc[0][0]); acc[0][1] = fmaf(pB0, fB.y, acc[0][1]);
            acc[0][2] = fmaf(pB0, fB.z, acc[0][2]); acc[0][3] = fmaf(pB0, fB.w, acc[0][3]);
            acc[1][0] = fmaf(pB1, fB.x, acc[1][0]); acc[1][1] = fmaf(pB1, fB.y, acc[1][1]);
            acc[1][2] = fmaf(pB1, fB.z, acc[1][2]); acc[1][3] = fmaf(pB1, fB.w, acc[1][3]);
            acc[2][0] = fmaf(pB2, fB.x, acc[2][0]); acc[2][1] = fmaf(pB2, fB.y, acc[2][1]);
            acc[2][2] = fmaf(pB2, fB.z, acc[2][2]); acc[2][3] = fmaf(pB2, fB.w, acc[2][3]);
            acc[3][0] = fmaf(pB3, fB.x, acc[3][0]); acc[3][1] = fmaf(pB3, fB.y, acc[3][1]);
            acc[3][2] = fmaf(pB3, fB.z, acc[3][2]); acc[3][3] = fmaf(pB3, fB.w, acc[3][3]);
        }
        if (k < nnb) {
            const float2 m = nb_meta[g][k];
            const float4 cc = *reinterpret_cast<const float4*>(
                &s_sc1[__float_as_int(m.y) + c2b]);
            const float t0 = m.x - cc.x, t1 = m.x - cc.y;
            const float t2 = m.x - cc.z, t3 = m.x - cc.w;
            const float p0 = ex2(-t0 * t0), p1 = ex2(-t1 * t1);
            const float p2 = ex2(-t2 * t2), p3 = ex2(-t3 * t3);
            const float4 f = nb_f4[g][k];
            acc[0][0] = fmaf(p0, f.x, acc[0][0]); acc[0][1] = fmaf(p0, f.y, acc[0][1]);
            acc[0][2] = fmaf(p0, f.z, acc[0][2]); acc[0][3] = fmaf(p0, f.w, acc[0][3]);
            acc[1][0] = fmaf(p1, f.x, acc[1][0]); acc[1][1] = fmaf(p1, f.y, acc[1][1]);
            acc[1][2] = fmaf(p1, f.z, acc[1][2]); acc[1][3] = fmaf(p1, f.w, acc[1][3]);
            acc[2][0] = fmaf(p2, f.x, acc[2][0]); acc[2][1] = fmaf(p2, f.y, acc[2][1]);
            acc[2][2] = fmaf(p2, f.z, acc[2][2]); acc[2][3] = fmaf(p2, f.w, acc[2][3]);
            acc[3][0] = fmaf(p3, f.x, acc[3][0]); acc[3][1] = fmaf(p3, f.y, acc[3][1]);
            acc[3][2] = fmaf(p3, f.z, acc[3][2]); acc[3][3] = fmaf(p3, f.w, acc[3][3]);
        }
        #pragma unroll
        for (int a = 0; a < 4; a++)
            #pragma unroll
            for (int f = 0; f < 4; f++) {
                float v = acc[a][f];
                v += __shfl_xor_sync(0xffffffffu, v, 1);
                v += __shfl_xor_sync(0xffffffffu, v, 2);
                acc[a][f] = v;
            }
        if (slice == 0) {
            // f-minor write: one float4 per c2 holds (f0..f3)
            #pragma unroll
            for (int a = 0; a < 4; a++)
                LmTf[g][c2b + a] =
                    make_float4(acc[a][0], acc[a][1], acc[a][2], acc[a][3]);
        }
    }
    __syncthreads();

    // ---- Warp-per-atom epilogue on f-minor layout: Gram -> rf -> scaled copy ----
    if (warp < GA) {
        const int g2 = warp;
        const float4 A0 = LmTf[g2][lane];
        const float4 A1 = LmTf[g2][lane + 32];
        // 10 Gram partials, statically unrolled
        float G0 = fmaf(A1.x, A1.x, A0.x * A0.x);
        float G1 = fmaf(A1.x, A1.y, A0.x * A0.y);
        float G2 = fmaf(A1.x, A1.z, A0.x * A0.z);
        float G3 = fmaf(A1.x, A1.w, A0.x * A0.w);
        float G4 = fmaf(A1.y, A1.y, A0.y * A0.y);
        float G5 = fmaf(A1.y, A1.z, A0.y * A0.z);
        float G6 = fmaf(A1.y, A1.w, A0.y * A0.w);
        float G7 = fmaf(A1.z, A1.z, A0.z * A0.z);
        float G8 = fmaf(A1.z, A1.w, A0.z * A0.w);
        float G9 = fmaf(A1.w, A1.w, A0.w * A0.w);
        #pragma unroll
        for (int o = 16; o > 0; o >>= 1) {
            G0 += __shfl_xor_sync(0xffffffffu, G0, o);
            G1 += __shfl_xor_sync(0xffffffffu, G1, o);
            G2 += __shfl_xor_sync(0xffffffffu, G2, o);
            G3 += __shfl_xor_sync(0xffffffffu, G3, o);
            G4 += __shfl_xor_sync(0xffffffffu, G4, o);
            G5 += __shfl_xor_sync(0xffffffffu, G5, o);
            G6 += __shfl_xor_sync(0xffffffffu, G6, o);
            G7 += __shfl_xor_sync(0xffffffffu, G7, o);
            G8 += __shfl_xor_sync(0xffffffffu, G8, o);
            G9 += __shfl_xor_sync(0xffffffffu, G9, o);
        }
        const float dsum = G0 * G0 + G4 * G4 + G7 * G7 + G9 * G9;
        const float osum = G1 * G1 + G2 * G2 + G3 * G3
                         + G5 * G5 + G6 * G6 + G8 * G8;
        const float rfv = rsqrtf(dsum + 2.0f * osum);
        LmTsf[g2][lane] =
            make_float4(A0.x * rfv, A0.y * rfv, A0.z * rfv, A0.w * rfv);
        LmTsf[g2][lane + 32] =
            make_float4(A1.x * rfv, A1.y * rfv, A1.z * rfv, A1.w * rfv);
    }
    __syncthreads();

    // ---- Phase 3: R = Lm (rf*Lm)^T; f-minor a-loads + packed f32x2 FMA ----
    const int dd0 = (tid * 4) & 63;
    const int crw = tid >> 4;                        // 0..7
    #pragma unroll
    for (int g2 = 0; g2 < GA; g2++) {
        // hoisted b-vectors: one float4 per dd gives (f0..f3); transpose-pack once
        const float4 bv0 = LmTsf[g2][dd0 + 0];
        const float4 bv1 = LmTsf[g2][dd0 + 1];
        const float4 bv2 = LmTsf[g2][dd0 + 2];
        const float4 bv3 = LmTsf[g2][dd0 + 3];
        const u64 b0xy = pk2(bv0.x, bv1.x), b0zw = pk2(bv2.x, bv3.x);
        const u64 b1xy = pk2(bv0.y, bv1.y), b1zw = pk2(bv2.y, bv3.y);
        const u64 b2xy = pk2(bv0.z, bv1.z), b2zw = pk2(bv2.z, bv3.z);
        const u64 b3xy = pk2(bv0.w, bv1.w), b3zw = pk2(bv2.w, bv3.w);
        float* ob = out + ((size_t)(bidx * GA + g2) << 12);
        #pragma unroll
        for (int grp = 0; grp < 8; grp++) {
            const int c = grp * 8 + crw;
            const float4 A = LmTf[g2][c];            // all 4 features, one LDS.128
            const u64 pa0 = pk2(A.x, A.x);
            const u64 pa1 = pk2(A.y, A.y);
            const u64 pa2 = pk2(A.z, A.z);
            const u64 pa3 = pk2(A.w, A.w);
            const u64 sxy = fma2(pa3, b3xy, fma2(pa2, b2xy, fma2(pa1, b1xy, mul2(pa0, b0xy))));
            const u64 szw = fma2(pa3, b3zw, fma2(pa2, b2zw, fma2(pa1, b1zw, mul2(pa0, b0zw))));
            float* ptr = ob + (grp << 9) + tid * 4;
            asm volatile("st.global.v2.b64 [%0], {%1, %2};"
                         :: "l"(ptr), "l"(sxy), "l"(szw) : "memory");
        }
    }
}

extern "C" void kernel_launch(void* const* d_in, const int* in_sizes, int n_in,
                              void* d_out, int out_size)
{
    // metadata order: boxs, numbers, coords, nuww0, sigmas0, centres0, nuww1, sigmas1, centres1
    const int*   numbers  = (const int*)  d_in[1];
    const float* coords   = (const float*)d_in[2];
    const float* nuww0    = (const float*)d_in[3];
    const float* sigmas0  = (const float*)d_in[4];
    const float* centres0 = (const float*)d_in[5];
    const float* nuww1    = (const float*)d_in[6];
    const float* sigmas1  = (const float*)d_in[7];
    const float* centres1 = (const float*)d_in[8];
    float* out = (float*)d_out;

    descriptor_kernel<<<(NBATCH * NATOM) / GA, NTHR>>>(
        numbers, coords, nuww0, sigmas0, centres0, nuww1, sigmas1, centres1, out);
}

// round 15
// speedup vs baseline: 1.0020x; 1.0020x over previous
#include <cuda_runtime.h>
#include <math.h>

#define NBATCH 4
#define NATOM  512
#define NSYM   4
#define NLAB   16
#define C1     32
#define C2     64
#define NTHR   128
#define GA     2          // atoms per CTA
#define MAXNB  96         // multiple of 8 (pad target)
#define C0P    36         // padded centres0 row (floats); 144B rows, 16B-aligned
#define C1P    68         // padded centres1 row (floats); 272B rows, 16B-aligned
#define SQK    1.2011224087864498f   // sqrt(log2(e))

typedef unsigned long long u64;

__device__ __forceinline__ float ex2(float x) {
    float r; asm("ex2.approx.ftz.f32 %0, %1;" : "=f"(r) : "f"(x)); return r;
}
__device__ __forceinline__ u64 pk2(float lo, float hi) {
    u64 r; asm("mov.b64 %0, {%1, %2};" : "=l"(r) : "f"(lo), "f"(hi)); return r;
}
__device__ __forceinline__ u64 fma2(u64 a, u64 b, u64 c) {
    u64 r; asm("fma.rn.f32x2 %0, %1, %2, %3;" : "=l"(r) : "l"(a), "l"(b), "l"(c)); return r;
}
__device__ __forceinline__ u64 mul2(u64 a, u64 b) {
    u64 r; asm("mul.rn.f32x2 %0, %1, %2;" : "=l"(r) : "l"(a), "l"(b)); return r;
}

__global__ __launch_bounds__(NTHR)
void descriptor_kernel(const int*   __restrict__ numbers,
                       const float* __restrict__ coords,
                       const float* __restrict__ nuww0,
                       const float* __restrict__ sigmas0,
                       const float* __restrict__ centres0,
                       const float* __restrict__ nuww1,
                       const float* __restrict__ sigmas1,
                       const float* __restrict__ centres1,
                       float*       __restrict__ out)
{
    __shared__ float4 s_pos[NATOM];                  // 8 KB
    __shared__ float  s_c0s[NLAB * C0P];             // 2.25 KB (c0*s0*SQK, padded)
    __shared__ float  s_sc1[NLAB * C1P];             // 4.25 KB (c1*s1*SQK, padded)
    __shared__ float  s_w0[NLAB], s_s0f[NLAB], s_w1[NLAB], s_s1f[NLAB];
    __shared__ float4 nb_f4[GA][MAXNB];              // 3 KB  (w1*fc, w1*gx, w1*gy, w1*gz)
    __shared__ float2 nb_meta[GA][MAXNB];            // 1.5 KB (rs*s1*SQK, row offset)
    __shared__ int    nb_j[GA][MAXNB];               // 0.75 KB (neighbor index only)
    __shared__ float4 LmTf [GA][C2];                 // 2 KB  f-minor: [c2] -> (f0..f3)
    __shared__ u64    LmTsd[GA][C2][4];              // 4 KB  rf-scaled, duplicated-packed
    __shared__ int    s_wcnt[GA][4];

    const int tid  = threadIdx.x;
    const int bidx = blockIdx.x;
    const int b    = bidx >> 8;                      // 256 CTAs per batch
    const int li0  = (bidx & 255) * GA;
    const int lane = tid & 31;
    const int warp = tid >> 5;
    const int g    = tid >> 6;                       // atom served (0/1) in later phases
    const int t64  = tid & 63;

    // ---- cooperative loads + folded table pre-scaling (float4 paths) ----
    {
        const float* cb  = coords  + (size_t)b * NATOM * 3;
        const int*   nbp = numbers + (size_t)b * NATOM;
        for (int t = tid; t < NATOM; t += NTHR)
            s_pos[t] = make_float4(cb[t * 3 + 0], cb[t * 3 + 1], cb[t * 3 + 2],
                                   __int_as_float(nbp[t]));
        // centres0: 512 floats = 128 float4, one sweep
        {
            const float4 v = reinterpret_cast<const float4*>(centres0)[tid];
            const int lab = tid >> 3;                // 8 float4 per row
            const float s = sigmas0[lab] * SQK;
            *reinterpret_cast<float4*>(&s_c0s[lab * C0P + (tid & 7) * 4]) =
                make_float4(v.x * s, v.y * s, v.z * s, v.w * s);
        }
        // centres1: 1024 floats = 256 float4, two sweeps
        #pragma unroll
        for (int r = 0; r < 2; r++) {
            const int idx = tid + r * NTHR;
            const float4 v = reinterpret_cast<const float4*>(centres1)[idx];
            const int lab = idx >> 4;                // 16 float4 per row
            const float s = sigmas1[lab] * SQK;
            *reinterpret_cast<float4*>(&s_sc1[lab * C1P + (idx & 15) * 4]) =
                make_float4(v.x * s, v.y * s, v.z * s, v.w * s);
        }
        if (tid < NLAB) {
            s_w0[tid]  = nuww0[tid];  s_s0f[tid] = sigmas0[tid] * SQK;
            s_w1[tid]  = nuww1[tid];  s_s1f[tid] = sigmas1[tid] * SQK;
        }
    }
    __syncthreads();

    // ---- Phase 1a: shared-j test + index-only compaction ----
    {
        const float4 ci0 = s_pos[li0];
        const float4 ci1 = s_pos[li0 + 1];

        unsigned mk0[4], mk1[4];
        int cnt0 = 0, cnt1 = 0;
        #pragma unroll
        for (int c = 0; c < 4; c++) {
            const int j = warp * 128 + c * 32 + lane;
            const float4 p = s_pos[j];
            const float dx0 = p.x - ci0.x, dy0 = p.y - ci0.y, dz0 = p.z - ci0.z;
            const float dx1 = p.x - ci1.x, dy1 = p.y - ci1.y, dz1 = p.z - ci1.z;
            const float d20 = dx0 * dx0 + dy0 * dy0 + dz0 * dz0;
            const float d21 = dx1 * dx1 + dy1 * dy1 + dz1 * dz1;
            const bool f0 = (j != li0)     && (d20 <= 36.0f);
            const bool f1 = (j != li0 + 1) && (d21 <= 36.0f);
            mk0[c] = __ballot_sync(0xffffffffu, f0);
            mk1[c] = __ballot_sync(0xffffffffu, f1);
            cnt0 += __popc(mk0[c]);
            cnt1 += __popc(mk1[c]);
        }
        if (lane == 0) { s_wcnt[0][warp] = cnt0; s_wcnt[1][warp] = cnt1; }
        __syncthreads();

        int base0 = 0, base1 = 0;
        #pragma unroll
        for (int w = 0; w < 4; w++) {
            if (w < warp) { base0 += s_wcnt[0][w]; base1 += s_wcnt[1][w]; }
        }
        const unsigned ltmask = (1u << lane) - 1u;
        #pragma unroll
        for (int c = 0; c < 4; c++) {
            const int j = warp * 128 + c * 32 + lane;
            if ((mk0[c] >> lane) & 1u) {
                const int pos = base0 + __popc(mk0[c] & ltmask);
                if (pos < MAXNB) nb_j[0][pos] = j;
            }
            base0 += __popc(mk0[c]);
            if ((mk1[c] >> lane) & 1u) {
                const int pos = base1 + __popc(mk1[c] & ltmask);
                if (pos < MAXNB) nb_j[1][pos] = j;
            }
            base1 += __popc(mk1[c]);
        }
    }
    __syncthreads();

    const int nnb  = min(s_wcnt[g][0] + s_wcnt[g][1] +
                         s_wcnt[g][2] + s_wcnt[g][3], MAXNB);
    const int nnbp = (nnb + 7) & ~7;                 // padded (<= MAXNB since 96%8==0)

    // ---- Phase 1b: geometry + first RConv (4 thr/pair, 16 pairs/sweep) ----
    // Writes zero-feature pad entries for p in [nnb, nnbp).
    {
        const float4 ci = s_pos[li0 + g];
        const int zbase = __float_as_int(ci.w) * NSYM;
        const int sub  = t64 & 3;                    // channel group of 8
        const int slot = t64 >> 2;                   // 0..15
        const int nIter = (nnbp + 15) >> 4;          // warp-uniform (same g per warp)
        for (int it = 0; it < nIter; it++) {
            const int p  = slot + (it << 4);
            const int pc = (p < nnb) ? p : (nnb - 1);
            const int j  = nb_j[g][pc];
            const float4 pj = s_pos[j];
            const float dx = pj.x - ci.x, dy = pj.y - ci.y, dz = pj.z - ci.z;
            const float d2 = dx * dx + dy * dy + dz * dz;
            const float rinv = (d2 > 0.0f) ? rsqrtf(d2) : 0.0f;
            const float d    = d2 * rinv;
            const float fc   = 0.5f * __cosf(d * 0.52359877559829887f) + 0.5f;
            const int   lab  = zbase + __float_as_int(pj.w);
            const float fcs  = fc * s_s0f[lab];
            const float4 cA = *reinterpret_cast<const float4*>(&s_c0s[lab * C0P + sub * 8]);
            const float4 cB = *reinterpret_cast<const float4*>(&s_c0s[lab * C0P + sub * 8 + 4]);
            const float a0 = fcs - cA.x, a1 = fcs - cA.y, a2 = fcs - cA.z, a3 = fcs - cA.w;
            const float a4 = fcs - cB.x, a5 = fcs - cB.y, a6 = fcs - cB.z, a7 = fcs - cB.w;
            float sum = ex2(-a0 * a0) + ex2(-a1 * a1) + ex2(-a2 * a2) + ex2(-a3 * a3)
                      + ex2(-a4 * a4) + ex2(-a5 * a5) + ex2(-a6 * a6) + ex2(-a7 * a7);
            sum += __shfl_xor_sync(0xffffffffu, sum, 1);
            sum += __shfl_xor_sync(0xffffffffu, sum, 2);
            if (sub == 0 && p < nnbp) {
                const float w1 = s_w1[lab];
                const float rs = s_w0[lab] * sum;
                nb_meta[g][p] = make_float2(rs * s_s1f[lab],
                                            __int_as_float(lab * C1P));
                const float gg = rinv * fc * w1;
                if (p < nnb)
                    nb_f4[g][p] = make_float4(fc * w1, dx * gg, dy * gg, dz * gg);
                else
                    nb_f4[g][p] = make_float4(0.f, 0.f, 0.f, 0.f);  // pad: zero contribution
            }
        }
    }
    __syncthreads();

    // ---- Phase 2: second RConv + Lm. Uniform padded loop, scalar FMA ----
    {
        const int lw    = t64 >> 5;
        const int l5    = t64 & 31;
        const int grp   = l5 >> 2;
        const int slice = l5 & 3;
        const int c2b   = (lw * 8 + grp) * 4;

        float acc[4][4];                             // [c2i][f]
        #pragma unroll
        for (int a = 0; a < 4; a++)
            #pragma unroll
            for (int f = 0; f < 4; f++) acc[a][f] = 0.0f;

        for (int k = slice; k < nnbp; k += 8) {
            const float2 mA = nb_meta[g][k];
            const float2 mB = nb_meta[g][k + 4];
            const float4 ccA = *reinterpret_cast<const float4*>(
                &s_sc1[__float_as_int(mA.y) + c2b]);
            const float4 ccB = *reinterpret_cast<const float4*>(
                &s_sc1[__float_as_int(mB.y) + c2b]);
            const float tA0 = mA.x - ccA.x, tA1 = mA.x - ccA.y;
            const float tA2 = mA.x - ccA.z, tA3 = mA.x - ccA.w;
            const float tB0 = mB.x - ccB.x, tB1 = mB.x - ccB.y;
            const float tB2 = mB.x - ccB.z, tB3 = mB.x - ccB.w;
            const float pA0 = ex2(-tA0 * tA0), pA1 = ex2(-tA1 * tA1);
            const float pA2 = ex2(-tA2 * tA2), pA3 = ex2(-tA3 * tA3);
            const float pB0 = ex2(-tB0 * tB0), pB1 = ex2(-tB1 * tB1);
            const float pB2 = ex2(-tB2 * tB2), pB3 = ex2(-tB3 * tB3);
            const float4 fA = nb_f4[g][k];
            const float4 fB = nb_f4[g][k + 4];
            acc[0][0] = fmaf(pA0, fA.x, acc[0][0]); acc[0][1] = fmaf(pA0, fA.y, acc[0][1]);
            acc[0][2] = fmaf(pA0, fA.z, acc[0][2]); acc[0][3] = fmaf(pA0, fA.w, acc[0][3]);
            acc[1][0] = fmaf(pA1, fA.x, acc[1][0]); acc[1][1] = fmaf(pA1, fA.y, acc[1][1]);
            acc[1][2] = fmaf(pA1, fA.z, acc[1][2]); acc[1][3] = fmaf(pA1, fA.w, acc[1][3]);
            acc[2][0] = fmaf(pA2, fA.x, acc[2][0]); acc[2][1] = fmaf(pA2, fA.y, acc[2][1]);
            acc[2][2] = fmaf(pA2, fA.z, acc[2][2]); acc[2][3] = fmaf(pA2, fA.w, acc[2][3]);
            acc[3][0] = fmaf(pA3, fA.x, acc[3][0]); acc[3][1] = fmaf(pA3, fA.y, acc[3][1]);
            acc[3][2] = fmaf(pA3, fA.z, acc[3][2]); acc[3][3] = fmaf(pA3, fA.w, acc[3][3]);
            acc[0][0] = fmaf(pB0, fB.x, acc[0][0]); acc[0][1] = fmaf(pB0, fB.y, acc[0][1]);
            acc[0][2] = fmaf(pB0, fB.z, acc[0][2]); acc[0][3] = fmaf(pB0, fB.w, acc[0][3]);
            acc[1][0] = fmaf(pB1, fB.x, acc[1][0]); acc[1][1] = fmaf(pB1, fB.y, acc[1][1]);
            acc[1][2] = fmaf(pB1, fB.z, acc[1][2]); acc[1][3] = fmaf(pB1, fB.w, acc[1][3]);
            acc[2][0] = fmaf(pB2, fB.x, acc[2][0]); acc[2][1] = fmaf(pB2, fB.y, acc[2][1]);
            acc[2][2] = fmaf(pB2, fB.z, acc[2][2]); acc[2][3] = fmaf(pB2, fB.w, acc[2][3]);
            acc[3][0] = fmaf(pB3, fB.x, acc[3][0]); acc[3][1] = fmaf(pB3, fB.y, acc[3][1]);
            acc[3][2] = fmaf(pB3, fB.z, acc[3][2]); acc[3][3] = fmaf(pB3, fB.w, acc[3][3]);
        }
        #pragma unroll
        for (int a = 0; a < 4; a++)
            #pragma unroll
            for (int f = 0; f < 4; f++) {
                float v = acc[a][f];
                v += __shfl_xor_sync(0xffffffffu, v, 1);
                v += __shfl_xor_sync(0xffffffffu, v, 2);
                acc[a][f] = v;
            }
        if (slice == 0) {
            // f-minor write: one float4 per c2 holds (f0..f3)
            #pragma unroll
            for (int a = 0; a < 4; a++)
                LmTf[g][c2b + a] =
                    make_float4(acc[a][0], acc[a][1], acc[a][2], acc[a][3]);
        }
    }
    __syncthreads();

    // ---- Warp-per-atom epilogue: Gram -> rf -> duplicated-packed scaled A ----
    if (warp < GA) {
        const int g2 = warp;
        const float4 A0 = LmTf[g2][lane];
        const float4 A1 = LmTf[g2][lane + 32];
        // 10 Gram partials, statically unrolled
        float G0 = fmaf(A1.x, A1.x, A0.x * A0.x);
        float G1 = fmaf(A1.x, A1.y, A0.x * A0.y);
        float G2 = fmaf(A1.x, A1.z, A0.x * A0.z);
        float G3 = fmaf(A1.x, A1.w, A0.x * A0.w);
        float G4 = fmaf(A1.y, A1.y, A0.y * A0.y);
        float G5 = fmaf(A1.y, A1.z, A0.y * A0.z);
        float G6 = fmaf(A1.y, A1.w, A0.y * A0.w);
        float G7 = fmaf(A1.z, A1.z, A0.z * A0.z);
        float G8 = fmaf(A1.z, A1.w, A0.z * A0.w);
        float G9 = fmaf(A1.w, A1.w, A0.w * A0.w);
        #pragma unroll
        for (int o = 16; o > 0; o >>= 1) {
            G0 += __shfl_xor_sync(0xffffffffu, G0, o);
            G1 += __shfl_xor_sync(0xffffffffu, G1, o);
            G2 += __shfl_xor_sync(0xffffffffu, G2, o);
            G3 += __shfl_xor_sync(0xffffffffu, G3, o);
            G4 += __shfl_xor_sync(0xffffffffu, G4, o);
            G5 += __shfl_xor_sync(0xffffffffu, G5, o);
            G6 += __shfl_xor_sync(0xffffffffu, G6, o);
            G7 += __shfl_xor_sync(0xffffffffu, G7, o);
            G8 += __shfl_xor_sync(0xffffffffu, G8, o);
            G9 += __shfl_xor_sync(0xffffffffu, G9, o);
        }
        const float dsum = G0 * G0 + G4 * G4 + G7 * G7 + G9 * G9;
        const float osum = G1 * G1 + G2 * G2 + G3 * G3
                         + G5 * G5 + G6 * G6 + G8 * G8;
        const float rfv = rsqrtf(dsum + 2.0f * osum);
        // duplicated-packed scaled A: LmTsd[c2][f] = (rf*A_f, rf*A_f)
        {
            const float s0 = A0.x * rfv, s1 = A0.y * rfv;
            const float s2 = A0.z * rfv, s3 = A0.w * rfv;
            LmTsd[g2][lane][0] = pk2(s0, s0);
            LmTsd[g2][lane][1] = pk2(s1, s1);
            LmTsd[g2][lane][2] = pk2(s2, s2);
            LmTsd[g2][lane][3] = pk2(s3, s3);
        }
        {
            const float s0 = A1.x * rfv, s1 = A1.y * rfv;
            const float s2 = A1.z * rfv, s3 = A1.w * rfv;
            LmTsd[g2][lane + 32][0] = pk2(s0, s0);
            LmTsd[g2][lane + 32][1] = pk2(s1, s1);
            LmTsd[g2][lane + 32][2] = pk2(s2, s2);
            LmTsd[g2][lane + 32][3] = pk2(s3, s3);
        }
    }
    __syncthreads();

    // ---- Phase 3: R = (rf*Lm) Lm^T; duplicated A loads + packed f32x2 FMA ----
    const int dd0 = (tid * 4) & 63;
    const int crw = tid >> 4;                        // 0..7
    #pragma unroll
    for (int g2 = 0; g2 < GA; g2++) {
        // hoisted UNSCALED b-vectors; transpose-pack once per atom
        const float4 bv0 = LmTf[g2][dd0 + 0];
        const float4 bv1 = LmTf[g2][dd0 + 1];
        const float4 bv2 = LmTf[g2][dd0 + 2];
        const float4 bv3 = LmTf[g2][dd0 + 3];
        const u64 b0xy = pk2(bv0.x, bv1.x), b0zw = pk2(bv2.x, bv3.x);
        const u64 b1xy = pk2(bv0.y, bv1.y), b1zw = pk2(bv2.y, bv3.y);
        const u64 b2xy = pk2(bv0.z, bv1.z), b2zw = pk2(bv2.z, bv3.z);
        const u64 b3xy = pk2(bv0.w, bv1.w), b3zw = pk2(bv2.w, bv3.w);
        float* ob = out + ((size_t)(bidx * GA + g2) << 12);
        #pragma unroll
        for (int grp = 0; grp < 8; grp++) {
            const int c = grp * 8 + crw;
            const ulonglong2 q0 = *reinterpret_cast<const ulonglong2*>(&LmTsd[g2][c][0]);
            const ulonglong2 q1 = *reinterpret_cast<const ulonglong2*>(&LmTsd[g2][c][2]);
            const u64 sxy = fma2(q1.y, b3xy, fma2(q1.x, b2xy,
                             fma2(q0.y, b1xy, mul2(q0.x, b0xy))));
            const u64 szw = fma2(q1.y, b3zw, fma2(q1.x, b2zw,
                             fma2(q0.y, b1zw, mul2(q0.x, b0zw))));
            float* ptr = ob + (grp << 9) + tid * 4;
            asm volatile("st.global.v2.b64 [%0], {%1, %2};"
                         :: "l"(ptr), "l"(sxy), "l"(szw) : "memory");
        }
    }
}

extern "C" void kernel_launch(void* const* d_in, const int* in_sizes, int n_in,
                              void* d_out, int out_size)
{
    // metadata order: boxs, numbers, coords, nuww0, sigmas0, centres0, nuww1, sigmas1, centres1
    const int*   numbers  = (const int*)  d_in[1];
    const float* coords   = (const float*)d_in[2];
    const float* nuww0    = (const float*)d_in[3];
    const float* sigmas0  = (const float*)d_in[4];
    const float* centres0 = (const float*)d_in[5];
    const float* nuww1    = (const float*)d_in[6];
    const float* sigmas1  = (const float*)d_in[7];
    const float* centres1 = (const float*)d_in[8];
    float* out = (float*)d_out;

    descriptor_kernel<<<(NBATCH * NATOM) / GA, NTHR>>>(
        numbers, coords, nuww0, sigmas0, centres0, nuww1, sigmas1, centres1, out);
}